// round 16
// baseline (speedup 1.0000x reference)
#include <cuda_runtime.h>
#include <cuda_fp16.h>
#include <cstdint>
#include <float.h>
#include <math.h>

#define Bn 8
#define Tn 4096
#define Dn 512
#define Rn 1024
#define T2 2048
#define Cn 3072
#define KPA 512                    // hidden A storage K (hi only)
#define KPW 1024                   // hidden W^T K ([Wh,Wm])
#define BM 128
#define BN 128
#define A_BYTES (BM * 128)
#define B_BYTES (BN * 128)
#define STG_BYTES (A_BYTES + B_BYTES)
#define SMEM_DYN (3 * STG_BYTES + 2048)
#define QCAP 64

// ---------------- device scratch ----------------
__device__ __align__(16) unsigned short g_S [(size_t)Bn * T2 * 512];
__device__ __align__(16) unsigned short g_Dm[(size_t)Bn * T2 * 512];
__device__ __align__(16) unsigned short g_A2[(size_t)Bn * Cn * KPA];
__device__ __align__(16) unsigned short g_Wt[(size_t)Dn * KPW];
__device__ __align__(16) unsigned long long g_t2[(size_t)Bn * T2 * 64]; // 32 half-tiles x top2
__device__ float g_inv[Bn * Tn];
__device__ unsigned long long g_key[Bn * T2];
__device__ unsigned long long g_winner_u[Bn * T2];
__device__ int   g_srctok[Bn * Rn];
__device__ int   g_dsttok[Bn * Rn];
__device__ __align__(16) unsigned char g_merged[Bn * Tn];
__device__ int   g_col[Bn * Cn];

// ---------------- helpers ----------------
__device__ __forceinline__ uint32_t smem_u32(const void* p) {
    uint32_t a;
    asm("{ .reg .u64 t; cvta.to.shared.u64 t, %1; cvt.u32.u64 %0, t; }" : "=r"(a) : "l"(p));
    return a;
}
__device__ __forceinline__ void cp16(uint32_t dst, const void* src) {
    asm volatile("cp.async.cg.shared.global [%0], [%1], 16;\n" :: "r"(dst), "l"(src));
}
#define CP_COMMIT() asm volatile("cp.async.commit_group;\n" ::: "memory")
#define CP_WAIT1()  asm volatile("cp.async.wait_group 1;\n" ::: "memory")
__device__ __forceinline__ void ldm_x4(uint32_t a, uint32_t& r0, uint32_t& r1,
                                       uint32_t& r2, uint32_t& r3) {
    asm volatile("ldmatrix.sync.aligned.m8n8.x4.shared.b16 {%0,%1,%2,%3}, [%4];\n"
        : "=r"(r0), "=r"(r1), "=r"(r2), "=r"(r3) : "r"(a));
}
__device__ __forceinline__ void mma16816(float* c, const uint32_t* a, uint32_t b0, uint32_t b1) {
    asm volatile("mma.sync.aligned.m16n8k16.row.col.f32.f16.f16.f32 "
        "{%0,%1,%2,%3}, {%4,%5,%6,%7}, {%8,%9}, {%0,%1,%2,%3};\n"
        : "+f"(c[0]), "+f"(c[1]), "+f"(c[2]), "+f"(c[3])
        : "r"(a[0]), "r"(a[1]), "r"(a[2]), "r"(a[3]), "r"(b0), "r"(b1));
}
__device__ __forceinline__ unsigned fmono(float f) {
    unsigned u = __float_as_uint(f);
    return (u & 0x80000000u) ? ~u : (u | 0x80000000u);
}
__device__ __forceinline__ float imono(unsigned m) {
    return __uint_as_float((m & 0x80000000u) ? (m & 0x7FFFFFFFu) : ~m);
}
__device__ __forceinline__ unsigned long long umax64(unsigned long long a, unsigned long long b) {
    return a > b ? a : b;
}
__device__ __forceinline__ unsigned long long umin64(unsigned long long a, unsigned long long b) {
    return a < b ? a : b;
}

// ---------------- K1: norms + hi-only fp16 of normalized rows + fused W split ------------
__global__ void k_prep(const float* __restrict__ x, const float* __restrict__ W) {
    if (blockIdx.x < 512) {
        int n = blockIdx.x;
        for (int k = threadIdx.x; k < Dn; k += 256) {
            float w = W[(size_t)k * Dn + n];
            __half hh = __float2half_rn(w);
            unsigned short h = __half_as_ushort(hh);
            unsigned short m = __half_as_ushort(__float2half_rn(w - __half2float(hh)));
            size_t base = (size_t)n * KPW;
            g_Wt[base + k] = h; g_Wt[base + 512 + k] = m;
        }
    }
    int row = blockIdx.x * 8 + (threadIdx.x >> 5);
    int lane = threadIdx.x & 31;
    int b = row >> 12, t = row & 4095;
    const float4* p = (const float4*)(x + (size_t)row * Dn);
    float4 v[4]; float ss = 0.f;
#pragma unroll
    for (int i = 0; i < 4; i++) {
        v[i] = p[lane + 32 * i];
        ss += v[i].x * v[i].x + v[i].y * v[i].y + v[i].z * v[i].z + v[i].w * v[i].w;
    }
#pragma unroll
    for (int o = 16; o; o >>= 1) ss += __shfl_xor_sync(0xFFFFFFFFu, ss, o);
    float inv = 1.0f / fmaxf(sqrtf(ss), 1e-12f);
    float sc = 32.0f * inv;
    if (lane == 0) g_inv[row] = inv;
    int odd = t & 1, s = t >> 1;
    unsigned short* rp = (odd ? g_S : g_Dm) + ((size_t)(b * T2 + s)) * 512;
#pragma unroll
    for (int i = 0; i < 4; i++) {
        int k0 = 4 * (lane + 32 * i);
        float a[4] = {v[i].x * sc, v[i].y * sc, v[i].z * sc, v[i].w * sc};
        unsigned short hs[4];
#pragma unroll
        for (int j = 0; j < 4; j++) hs[j] = __half_as_ushort(__float2half_rn(a[j]));
        *(ushort4*)(rp + k0) = make_ushort4(hs[0], hs[1], hs[2], hs[3]);
    }
}

// ---------------- HMMA engine: C[128x128] = A[128xKA]*B[128xKB]^T, 256 thr ----------------
__device__ __forceinline__ void load_stage2(const unsigned short* Ab, const unsigned short* Bb,
                                            int KA, int KB, uint32_t sA, uint32_t sB,
                                            int ka, int kb, int tid) {
#pragma unroll
    for (int i = 0; i < 4; i++) {
        int u = tid + 256 * i, r = u >> 3, c = u & 7;
        int off = r * 128 + c * 16; off ^= (off >> 3) & 0x70;
        cp16(sA + off, Ab + (size_t)r * KA + ka + c * 8);
    }
#pragma unroll
    for (int i = 0; i < 4; i++) {
        int u = tid + 256 * i, r = u >> 3, c = u & 7;
        int off = r * 128 + c * 16; off ^= (off >> 3) & 0x70;
        cp16(sB + off, Bb + (size_t)r * KB + kb + c * 8);
    }
}

// AMOD: hidden GEMM — A reads H segment twice (ns&7), W reads [Wh|Wm] linearly
template<int NST, bool AMOD>
__device__ __forceinline__ void gemm_tile(const unsigned short* Ab, const unsigned short* Bb,
                                          int KA, int KB, uint32_t smb, int tid,
                                          float acc[2][8][4]) {
    const int lane = tid & 31, w = tid >> 5;
    const int wr = w >> 1, wc = w & 1;
#pragma unroll
    for (int mi = 0; mi < 2; mi++)
#pragma unroll
        for (int ni = 0; ni < 8; ni++)
#pragma unroll
            for (int d = 0; d < 4; d++) acc[mi][ni][d] = 0.f;

    const int la = lane & 15, ka = (lane >> 4) * 16;
    uint32_t pA[2]; int xa[2];
#pragma unroll
    for (int mi = 0; mi < 2; mi++) {
        int row = wr * 32 + mi * 16 + la;
        pA[mi] = row * 128; xa[mi] = (row & 7) << 4;
    }
    const int lb = (lane & 7) + ((lane >> 4) & 1) * 8, kbB = ((lane >> 3) & 1) * 16;
    uint32_t pB[4]; int xb[4];
#pragma unroll
    for (int g = 0; g < 4; g++) {
        int row = wc * 64 + g * 16 + lb;
        pB[g] = row * 128; xb[g] = (row & 7) << 4;
    }

    load_stage2(Ab, Bb, KA, KB, smb, smb + A_BYTES, 0, 0, tid);
    CP_COMMIT();
    load_stage2(Ab, Bb, KA, KB, smb + STG_BYTES, smb + STG_BYTES + A_BYTES, 64, 64, tid);
    CP_COMMIT();
    for (int s = 0; s < NST; ++s) {
        CP_WAIT1();
        __syncthreads();
        if (s + 2 < NST) {
            int ns = s + 2, nb = ns % 3;
            int ka_off = (AMOD ? (ns & 7) : ns) * 64;
            load_stage2(Ab, Bb, KA, KB, smb + nb * STG_BYTES,
                        smb + nb * STG_BYTES + A_BYTES, ka_off, ns * 64, tid);
        }
        CP_COMMIT();
        const uint32_t sA = smb + (s % 3) * STG_BYTES;
        const uint32_t sB = sA + A_BYTES;
#pragma unroll
        for (int kk = 0; kk < 4; kk++) {
            const int kb = kk * 32;
            uint32_t a[2][4], bf[4][4];
#pragma unroll
            for (int mi = 0; mi < 2; mi++)
                ldm_x4(sA + pA[mi] + ((kb + ka) ^ xa[mi]),
                       a[mi][0], a[mi][1], a[mi][2], a[mi][3]);
#pragma unroll
            for (int g = 0; g < 4; g++)
                ldm_x4(sB + pB[g] + ((kb + kbB) ^ xb[g]),
                       bf[g][0], bf[g][1], bf[g][2], bf[g][3]);
#pragma unroll
            for (int mi = 0; mi < 2; mi++)
#pragma unroll
                for (int ni = 0; ni < 8; ni++) {
                    const int g = ni >> 1, p = ni & 1;
                    mma16816(acc[mi][ni], a[mi], bf[g][p * 2], bf[g][p * 2 + 1]);
                }
        }
    }
}

// ---------------- K3a: scores GEMM -> per-(row, 64-col half-tile) top-2 ----------------
__global__ __launch_bounds__(256, 2) void k_scores_hi() {
    extern __shared__ char smx[];
    const int n0 = blockIdx.x * BN, m0 = blockIdx.y * BM, b = blockIdx.z;
    const int tid = threadIdx.x, lane = tid & 31, w = tid >> 5;
    const int wr = w >> 1, wc = w & 1;
    float acc[2][8][4];
    gemm_tile<8, false>(g_S + ((size_t)(b * T2 + m0)) * 512,
                        g_Dm + ((size_t)(b * T2 + n0)) * 512, 512, 512,
                        smem_u32(smx), tid, acc);
#pragma unroll
    for (int mi = 0; mi < 2; mi++) {
#pragma unroll
        for (int hi = 0; hi < 2; hi++) {
            unsigned long long k1 = 0ull, k2 = 0ull;
#pragma unroll
            for (int ni = 0; ni < 8; ni++) {
#pragma unroll
                for (int d = 0; d < 2; d++) {
                    float v = acc[mi][ni][hi * 2 + d];
                    int col = n0 + wc * 64 + ni * 8 + 2 * (lane & 3) + d;
                    unsigned long long key =
                        ((unsigned long long)fmono(v) << 32) | (unsigned)col;
                    if (key > k1) { k2 = k1; k1 = key; }
                    else if (key > k2) k2 = key;
                }
            }
#pragma unroll
            for (int o = 1; o <= 2; o <<= 1) {
                unsigned long long o1 = __shfl_xor_sync(0xFFFFFFFFu, k1, o);
                unsigned long long o2 = __shfl_xor_sync(0xFFFFFFFFu, k2, o);
                unsigned long long n1 = umax64(k1, o1);
                unsigned long long n2 = umax64(umin64(k1, o1), umax64(k2, o2));
                k1 = n1; k2 = n2;
            }
            if ((lane & 3) == 0) {
                int row = m0 + wr * 32 + mi * 16 + (lane >> 2) + hi * 8;
                int ht = blockIdx.x * 2 + wc;
                *(ulonglong2*)(g_t2 + ((size_t)(b * T2 + row) * 32 + ht) * 2) =
                    make_ulonglong2(k1, k2);
            }
        }
    }
}

// ---------------- K3b: exact rescore of top-2 candidates ----------------
__global__ void k_cand(const float* __restrict__ x) {
    const int b = blockIdx.y;
    const int w = threadIdx.x >> 5;
    const int m = blockIdx.x * 8 + w;
    const int lane = threadIdx.x & 31;
    __shared__ int s_cnt[8];
    __shared__ int s_buf[8][QCAP];
    if (lane == 0) s_cnt[w] = 0;
    __syncwarp();
    ulonglong2 e = ((const ulonglong2*)(g_t2 + (size_t)(b * T2 + m) * 64))[lane];
    unsigned long long mx = e.x;
#pragma unroll
    for (int o = 16; o; o >>= 1) mx = umax64(mx, __shfl_xor_sync(0xFFFFFFFFu, mx, o));
    float tmaxv = imono((unsigned)(mx >> 32));
    unsigned thrm = fmono(tmaxv - 0.65f);   // 2x GEMM 5-sigma + margin (fp32 values)
    if ((unsigned)(e.x >> 32) >= thrm) {
        int ix = atomicAdd(&s_cnt[w], 1);
        if (ix < QCAP) s_buf[w][ix] = (int)(e.x & 0xFFFFFFFFu);
    }
    if ((unsigned)(e.y >> 32) >= thrm) {
        int ix = atomicAdd(&s_cnt[w], 1);
        if (ix < QCAP) s_buf[w][ix] = (int)(e.y & 0xFFFFFFFFu);
    }
    __syncwarp();
    int cnt = min(s_cnt[w], QCAP);
    const float* xb = x + (size_t)b * Tn * Dn;
    const float* xs = xb + (size_t)(2 * m + 1) * Dn;
    const float inv_s = g_inv[b * Tn + 2 * m + 1];
    float best = -FLT_MAX; int bcol = 0x7FFFFFFF;
    for (int c = 0; c < cnt; c++) {
        int j = s_buf[w][c];
        const float* xd = xb + (size_t)(2 * j) * Dn;
        float acc = 0.f;
#pragma unroll
        for (int i = 0; i < 4; i++) {
            int k = lane * 4 + i * 128;
            float4 a = *(const float4*)(xs + k);
            float4 d = *(const float4*)(xd + k);
            acc += a.x * d.x + a.y * d.y + a.z * d.z + a.w * d.w;
        }
#pragma unroll
        for (int o = 16; o; o >>= 1) acc += __shfl_xor_sync(0xFFFFFFFFu, acc, o);
        float ev = acc * inv_s * g_inv[b * Tn + 2 * j];
        if (ev > best || (ev == best && j < bcol)) { best = ev; bcol = j; }
    }
    if (lane == 0)
        g_key[b * T2 + m] = ((unsigned long long)fmono(best) << 32) | (unsigned)(2047 - bcol);
}

// ---------------- K4: bisection top-k select (1 barrier/iter) + compaction --------------
__global__ __launch_bounds__(1024) void k_select() {
    const int b = blockIdx.x, tid = threadIdx.x;
    const int lane = tid & 31, w = tid >> 5;
    __shared__ int s_cntArr[36];
    __shared__ unsigned s_bitmap[64], s_wpre[64];
    __shared__ int s_warpsum[32];
    __shared__ int s_ns;

    unsigned long long kv0 = g_key[b * T2 + tid];
    unsigned long long kv1 = g_key[b * T2 + tid + 1024];
    unsigned m0 = (unsigned)(kv0 >> 32), m1 = (unsigned)(kv1 >> 32);
    g_winner_u[b * T2 + tid] = 0ull;
    g_winner_u[b * T2 + tid + 1024] = 0ull;
    ((unsigned*)(g_merged + (size_t)b * Tn))[tid] = 0u;
    if (tid < 36) s_cntArr[tid] = 0;
    if (tid < 64) s_bitmap[tid] = 0u;
    if (tid == 0) s_ns = 0;
    __syncthreads();

    unsigned lo = 0u, hi = 0xFFFFFFFFu;
    for (int it = 0; lo < hi; ++it) {
        unsigned mid = lo + ((hi - lo) >> 1) + 1u;
        int c = __popc(__ballot_sync(0xFFFFFFFFu, m0 >= mid))
              + __popc(__ballot_sync(0xFFFFFFFFu, m1 >= mid));
        if (lane == 0 && c) atomicAdd(&s_cntArr[it], c);
        __syncthreads();
        if (s_cntArr[it] >= Rn) lo = mid; else hi = mid - 1u;
    }
    const unsigned vstar = lo;
    {
        int cg = __popc(__ballot_sync(0xFFFFFFFFu, m0 > vstar))
               + __popc(__ballot_sync(0xFFFFFFFFu, m1 > vstar));
        if (lane == 0 && cg) atomicAdd(&s_cntArr[34], cg);
    }
    if (m0 == vstar) atomicOr(&s_bitmap[tid >> 5], 1u << (tid & 31));
    if (m1 == vstar) atomicOr(&s_bitmap[(tid + 1024) >> 5], 1u << (tid & 31));
    __syncthreads();
    const unsigned quota = Rn - (unsigned)s_cntArr[34];
    if (tid == 0) {
        unsigned run = 0;
        for (int w2 = 0; w2 < 64; w2++) { s_wpre[w2] = run; run += __popc(s_bitmap[w2]); }
    }
    __syncthreads();

#pragma unroll
    for (int e = 0; e < 2; e++) {
        int i = tid + e * 1024;
        unsigned mo = e ? m1 : m0;
        unsigned long long kv = e ? kv1 : kv0;
        bool sel = mo > vstar;
        if (!sel && mo == vstar) {
            unsigned r = s_wpre[i >> 5] + __popc(s_bitmap[i >> 5] & ((1u << (i & 31)) - 1u));
            sel = r < quota;
        }
        if (sel) {
            int slot = atomicAdd(&s_ns, 1);
            int stok = 2 * i + 1;
            int dl = 2047 - (int)(kv & 0xFFFFFFFFu);
            g_srctok[b * Rn + slot] = stok;
            g_dsttok[b * Rn + slot] = 2 * dl;
            g_merged[(size_t)b * Tn + stok] = 1;
            unsigned long long wkey = ((unsigned long long)(~mo) << 32) | (unsigned)i;
            atomicMax(&g_winner_u[(size_t)b * T2 + dl], wkey);
        }
    }
    __syncthreads();

    const int base = tid * 4;
    int loc[4]; int c0 = 0;
#pragma unroll
    for (int i = 0; i < 4; i++) {
        loc[i] = g_merged[(size_t)b * Tn + base + i] ? 0 : 1;
        c0 += loc[i];
    }
    int inc = c0;
#pragma unroll
    for (int o = 1; o < 32; o <<= 1) {
        int v = __shfl_up_sync(0xFFFFFFFFu, inc, o);
        if (lane >= o) inc += v;
    }
    if (lane == 31) s_warpsum[w] = inc;
    __syncthreads();
    if (w == 0) {
        int v = s_warpsum[lane];
        int sc = v;
#pragma unroll
        for (int o = 1; o < 32; o <<= 1) {
            int u = __shfl_up_sync(0xFFFFFFFFu, sc, o);
            if (lane >= o) sc += u;
        }
        s_warpsum[lane] = sc - v;
    }
    __syncthreads();
    int run = s_warpsum[w] + inc - c0;
#pragma unroll
    for (int i = 0; i < 4; i++)
        if (loc[i]) { g_col[b * Cn + run] = base + i; run++; }
}

// ---------------- K6: merged matrix, hi-only fp16 ----------------
__global__ void k_build2(const float* __restrict__ x) {
    const int b = blockIdx.y, c = blockIdx.x;
    const int t = g_col[b * Cn + c];
    const int tid = threadIdx.x; // 128
    const float* xb = x + (size_t)b * Tn * Dn;
    float4 v = *(const float4*)(xb + (size_t)t * Dn + tid * 4);
    if ((t & 1) == 0) {
        unsigned long long w = g_winner_u[(size_t)b * T2 + (t >> 1)];
        if (w) {
            int si = (int)(w & 0xFFFFFFFFu);
            const float4* up = (const float4*)(xb + (size_t)(2 * si + 1) * Dn);
            float4 u = up[tid];
            v.x = (u.x + v.x) * 0.5f; v.y = (u.y + v.y) * 0.5f;
            v.z = (u.z + v.z) * 0.5f; v.w = (u.w + v.w) * 0.5f;
        }
    }
    unsigned short* rp = g_A2 + ((size_t)(b * Cn + c)) * KPA;
    unsigned short hs[4];
    hs[0] = __half_as_ushort(__float2half_rn(v.x));
    hs[1] = __half_as_ushort(__float2half_rn(v.y));
    hs[2] = __half_as_ushort(__float2half_rn(v.z));
    hs[3] = __half_as_ushort(__float2half_rn(v.w));
    *(ushort4*)(rp + tid * 4) = make_ushort4(hs[0], hs[1], hs[2], hs[3]);
}

// ---------------- K7: hidden GEMM (AhWh + AhWm) + scattered epilogue ----------------
__global__ __launch_bounds__(256, 2) void k_hidden_mma(const float* __restrict__ bias,
                                                       float* __restrict__ out) {
    extern __shared__ char smx[];
    const int n0 = blockIdx.x * BN, m0 = blockIdx.y * BM;
    const int b = m0 / Cn, cm0 = m0 % Cn;
    const int tid = threadIdx.x, lane = tid & 31, w = tid >> 5;
    const int wr = w >> 1, wc = w & 1;
    int*   s_tok  = (int*)(smx + 3 * STG_BYTES);
    float* s_bias = (float*)(smx + 3 * STG_BYTES + 512 + 64);
    if (tid < 128) s_tok[tid] = g_col[b * Cn + cm0 + tid];
    if (tid >= 128 && tid < 256) s_bias[tid - 128] = bias[n0 + tid - 128];
    __syncthreads();
    float acc[2][8][4];
    gemm_tile<16, true>(g_A2 + (size_t)m0 * KPA, g_Wt + (size_t)n0 * KPW,
                        KPA, KPW, smem_u32(smx), tid, acc);
#pragma unroll
    for (int mi = 0; mi < 2; mi++) {
#pragma unroll
        for (int hi = 0; hi < 2; hi++) {
            int row = wr * 32 + mi * 16 + (lane >> 2) + hi * 8;
            int tok = s_tok[row];
            float* op = out + (size_t)b * Tn * Dn + (size_t)tok * Dn + n0;
#pragma unroll
            for (int ni = 0; ni < 8; ni++) {
                int col = wc * 64 + ni * 8 + 2 * (lane & 3);
                float2 o;
                o.x = acc[mi][ni][hi * 2 + 0] + s_bias[col + 0];
                o.y = acc[mi][ni][hi * 2 + 1] + s_bias[col + 1];
                *(float2*)(op + col) = o;
            }
        }
    }
}

// ---------------- K8: out[src] = out[dst], 4 pairs per block ----------------
__global__ void k_copy(float* __restrict__ out) {
    const int b = blockIdx.y;
    const int i = blockIdx.x * 4 + (threadIdx.x >> 7);
    const int tid = threadIdx.x & 127;
    const int st = g_srctok[b * Rn + i], dt = g_dsttok[b * Rn + i];
    const float4* src = (const float4*)(out + (size_t)b * Tn * Dn + (size_t)dt * Dn);
    float4* dst = (float4*)(out + (size_t)b * Tn * Dn + (size_t)st * Dn);
    dst[tid] = src[tid];
}

extern "C" void kernel_launch(void* const* d_in, const int* in_sizes, int n_in,
                              void* d_out, int out_size) {
    const float* x    = (const float*)d_in[0];
    const float* W    = (const float*)d_in[1];
    const float* bias = (const float*)d_in[2];
    float* out = (float*)d_out;

    static int cfg = 0;
    if (!cfg) {
        cudaFuncSetAttribute(k_scores_hi, cudaFuncAttributeMaxDynamicSharedMemorySize, SMEM_DYN);
        cudaFuncSetAttribute(k_hidden_mma, cudaFuncAttributeMaxDynamicSharedMemorySize, SMEM_DYN);
        cfg = 1;
    }

    k_prep<<<Bn * Tn / 8, 256>>>(x, W);
    k_scores_hi<<<dim3(T2 / BN, T2 / BM, Bn), 256, SMEM_DYN>>>();
    k_cand<<<dim3(T2 / 8, Bn), 256>>>(x);
    k_select<<<Bn, 1024>>>();
    k_build2<<<dim3(Cn, Bn), 128>>>(x);
    k_hidden_mma<<<dim3(Dn / BN, (Bn * Cn) / BM), 256, SMEM_DYN>>>(bias, out);
    k_copy<<<dim3(Rn / 4, Bn), 512>>>(out);
}

// round 17
// speedup vs baseline: 1.0196x; 1.0196x over previous
#include <cuda_runtime.h>
#include <cuda_fp16.h>
#include <cstdint>
#include <float.h>
#include <math.h>

#define Bn 8
#define Tn 4096
#define Dn 512
#define Rn 1024
#define T2 2048
#define Cn 3072
#define KPA 512                    // hidden A storage K (hi only)
#define KPW 1024                   // hidden W^T K ([Wh,Wm])
#define BM 128
#define BN 128
#define A_BYTES (BM * 128)
#define B_BYTES (BN * 128)
#define STG_BYTES (A_BYTES + B_BYTES)
#define SMEM_DYN (3 * STG_BYTES + 2048)
#define CAND_CAP 160

// ---------------- device scratch ----------------
__device__ __align__(16) unsigned short g_S [(size_t)Bn * T2 * 512];
__device__ __align__(16) unsigned short g_Dm[(size_t)Bn * T2 * 512];
__device__ __align__(16) unsigned short g_A2[(size_t)Bn * Cn * KPA];
__device__ __align__(16) unsigned short g_Wt[(size_t)Dn * KPW];
__device__ __align__(16) __half g_SCh[(size_t)Bn * T2 * T2];
__device__ __align__(16) unsigned g_tmax[(size_t)Bn * T2 * 16];
__device__ float g_inv[Bn * Tn];
__device__ unsigned long long g_key[Bn * T2];
__device__ unsigned long long g_winner_u[Bn * T2];
__device__ int   g_srctok[Bn * Rn];
__device__ int   g_dsttok[Bn * Rn];
__device__ __align__(16) unsigned char g_merged[Bn * Tn];
__device__ int   g_col[Bn * Cn];

// ---------------- helpers ----------------
__device__ __forceinline__ uint32_t smem_u32(const void* p) {
    uint32_t a;
    asm("{ .reg .u64 t; cvta.to.shared.u64 t, %1; cvt.u32.u64 %0, t; }" : "=r"(a) : "l"(p));
    return a;
}
__device__ __forceinline__ void cp16(uint32_t dst, const void* src) {
    asm volatile("cp.async.cg.shared.global [%0], [%1], 16;\n" :: "r"(dst), "l"(src));
}
#define CP_COMMIT() asm volatile("cp.async.commit_group;\n" ::: "memory")
#define CP_WAIT1()  asm volatile("cp.async.wait_group 1;\n" ::: "memory")
__device__ __forceinline__ void ldm_x4(uint32_t a, uint32_t& r0, uint32_t& r1,
                                       uint32_t& r2, uint32_t& r3) {
    asm volatile("ldmatrix.sync.aligned.m8n8.x4.shared.b16 {%0,%1,%2,%3}, [%4];\n"
        : "=r"(r0), "=r"(r1), "=r"(r2), "=r"(r3) : "r"(a));
}
__device__ __forceinline__ void mma16816(float* c, const uint32_t* a, uint32_t b0, uint32_t b1) {
    asm volatile("mma.sync.aligned.m16n8k16.row.col.f32.f16.f16.f32 "
        "{%0,%1,%2,%3}, {%4,%5,%6,%7}, {%8,%9}, {%0,%1,%2,%3};\n"
        : "+f"(c[0]), "+f"(c[1]), "+f"(c[2]), "+f"(c[3])
        : "r"(a[0]), "r"(a[1]), "r"(a[2]), "r"(a[3]), "r"(b0), "r"(b1));
}
__device__ __forceinline__ unsigned fmono(float f) {
    unsigned u = __float_as_uint(f);
    return (u & 0x80000000u) ? ~u : (u | 0x80000000u);
}
__device__ __forceinline__ float imono(unsigned m) {
    return __uint_as_float((m & 0x80000000u) ? (m & 0x7FFFFFFFu) : ~m);
}

// ---------------- K1: norms + hi-only fp16 of normalized rows + fused W split ------------
__global__ void k_prep(const float* __restrict__ x, const float* __restrict__ W) {
    if (blockIdx.x < 1024) g_tmax[(size_t)blockIdx.x * 256 + threadIdx.x] = 0u;
    if (blockIdx.x < 512) {
        int n = blockIdx.x;
        for (int k = threadIdx.x; k < Dn; k += 256) {
            float w = W[(size_t)k * Dn + n];
            __half hh = __float2half_rn(w);
            unsigned short h = __half_as_ushort(hh);
            unsigned short m = __half_as_ushort(__float2half_rn(w - __half2float(hh)));
            size_t base = (size_t)n * KPW;
            g_Wt[base + k] = h; g_Wt[base + 512 + k] = m;
        }
    }
    int row = blockIdx.x * 8 + (threadIdx.x >> 5);
    int lane = threadIdx.x & 31;
    int b = row >> 12, t = row & 4095;
    const float4* p = (const float4*)(x + (size_t)row * Dn);
    float4 v[4]; float ss = 0.f;
#pragma unroll
    for (int i = 0; i < 4; i++) {
        v[i] = p[lane + 32 * i];
        ss += v[i].x * v[i].x + v[i].y * v[i].y + v[i].z * v[i].z + v[i].w * v[i].w;
    }
#pragma unroll
    for (int o = 16; o; o >>= 1) ss += __shfl_xor_sync(0xFFFFFFFFu, ss, o);
    float inv = 1.0f / fmaxf(sqrtf(ss), 1e-12f);
    float sc = 32.0f * inv;
    if (lane == 0) g_inv[row] = inv;
    int odd = t & 1, s = t >> 1;
    unsigned short* rp = (odd ? g_S : g_Dm) + ((size_t)(b * T2 + s)) * 512;
#pragma unroll
    for (int i = 0; i < 4; i++) {
        int k0 = 4 * (lane + 32 * i);
        float a[4] = {v[i].x * sc, v[i].y * sc, v[i].z * sc, v[i].w * sc};
        unsigned short hs[4];
#pragma unroll
        for (int j = 0; j < 4; j++) hs[j] = __half_as_ushort(__float2half_rn(a[j]));
        *(ushort4*)(rp + k0) = make_ushort4(hs[0], hs[1], hs[2], hs[3]);
    }
}

// ---------------- HMMA engine: C[128x128] = A[128xKA]*B[128xKB]^T, 256 thr ----------------
__device__ __forceinline__ void load_stage2(const unsigned short* Ab, const unsigned short* Bb,
                                            int KA, int KB, uint32_t sA, uint32_t sB,
                                            int ka, int kb, int tid) {
#pragma unroll
    for (int i = 0; i < 4; i++) {
        int u = tid + 256 * i, r = u >> 3, c = u & 7;
        int off = r * 128 + c * 16; off ^= (off >> 3) & 0x70;
        cp16(sA + off, Ab + (size_t)r * KA + ka + c * 8);
    }
#pragma unroll
    for (int i = 0; i < 4; i++) {
        int u = tid + 256 * i, r = u >> 3, c = u & 7;
        int off = r * 128 + c * 16; off ^= (off >> 3) & 0x70;
        cp16(sB + off, Bb + (size_t)r * KB + kb + c * 8);
    }
}

// AMOD: hidden GEMM — A reads H segment twice (ns&7), W reads [Wh|Wm] linearly
template<int NST, bool AMOD>
__device__ __forceinline__ void gemm_tile(const unsigned short* Ab, const unsigned short* Bb,
                                          int KA, int KB, uint32_t smb, int tid,
                                          float acc[2][8][4]) {
    const int lane = tid & 31, w = tid >> 5;
    const int wr = w >> 1, wc = w & 1;
#pragma unroll
    for (int mi = 0; mi < 2; mi++)
#pragma unroll
        for (int ni = 0; ni < 8; ni++)
#pragma unroll
            for (int d = 0; d < 4; d++) acc[mi][ni][d] = 0.f;

    const int la = lane & 15, ka = (lane >> 4) * 16;
    uint32_t pA[2]; int xa[2];
#pragma unroll
    for (int mi = 0; mi < 2; mi++) {
        int row = wr * 32 + mi * 16 + la;
        pA[mi] = row * 128; xa[mi] = (row & 7) << 4;
    }
    const int lb = (lane & 7) + ((lane >> 4) & 1) * 8, kbB = ((lane >> 3) & 1) * 16;
    uint32_t pB[4]; int xb[4];
#pragma unroll
    for (int g = 0; g < 4; g++) {
        int row = wc * 64 + g * 16 + lb;
        pB[g] = row * 128; xb[g] = (row & 7) << 4;
    }

    load_stage2(Ab, Bb, KA, KB, smb, smb + A_BYTES, 0, 0, tid);
    CP_COMMIT();
    load_stage2(Ab, Bb, KA, KB, smb + STG_BYTES, smb + STG_BYTES + A_BYTES, 64, 64, tid);
    CP_COMMIT();
    for (int s = 0; s < NST; ++s) {
        CP_WAIT1();
        __syncthreads();
        if (s + 2 < NST) {
            int ns = s + 2, nb = ns % 3;
            int ka_off = (AMOD ? (ns & 7) : ns) * 64;
            load_stage2(Ab, Bb, KA, KB, smb + nb * STG_BYTES,
                        smb + nb * STG_BYTES + A_BYTES, ka_off, ns * 64, tid);
        }
        CP_COMMIT();
        const uint32_t sA = smb + (s % 3) * STG_BYTES;
        const uint32_t sB = sA + A_BYTES;
#pragma unroll
        for (int kk = 0; kk < 4; kk++) {
            const int kb = kk * 32;
            uint32_t a[2][4], bf[4][4];
#pragma unroll
            for (int mi = 0; mi < 2; mi++)
                ldm_x4(sA + pA[mi] + ((kb + ka) ^ xa[mi]),
                       a[mi][0], a[mi][1], a[mi][2], a[mi][3]);
#pragma unroll
            for (int g = 0; g < 4; g++)
                ldm_x4(sB + pB[g] + ((kb + kbB) ^ xb[g]),
                       bf[g][0], bf[g][1], bf[g][2], bf[g][3]);
#pragma unroll
            for (int mi = 0; mi < 2; mi++)
#pragma unroll
                for (int ni = 0; ni < 8; ni++) {
                    const int g = ni >> 1, p = ni & 1;
                    mma16816(acc[mi][ni], a[mi], bf[g][p * 2], bf[g][p * 2 + 1]);
                }
        }
    }
}

// ---------------- K3a: hi-only scores GEMM -> g_SCh + per-row per-tile max ----------------
__global__ __launch_bounds__(256, 2) void k_scores_hi() {
    extern __shared__ char smx[];
    const int n0 = blockIdx.x * BN, m0 = blockIdx.y * BM, b = blockIdx.z;
    const int tid = threadIdx.x, lane = tid & 31, w = tid >> 5;
    const int wr = w >> 1, wc = w & 1;
    float acc[2][8][4];
    gemm_tile<8, false>(g_S + ((size_t)(b * T2 + m0)) * 512,
                        g_Dm + ((size_t)(b * T2 + n0)) * 512, 512, 512,
                        smem_u32(smx), tid, acc);
#pragma unroll
    for (int mi = 0; mi < 2; mi++) {
#pragma unroll
        for (int hi = 0; hi < 2; hi++) {
            int row = m0 + wr * 32 + mi * 16 + (lane >> 2) + hi * 8;
            __half* SCr = g_SCh + ((size_t)(b * T2) + row) * T2 + n0 + wc * 64 + 2 * (lane & 3);
            float rmax = -FLT_MAX;
#pragma unroll
            for (int ni = 0; ni < 8; ni++) {
                float v0 = acc[mi][ni][hi * 2], v1 = acc[mi][ni][hi * 2 + 1];
                rmax = fmaxf(rmax, fmaxf(v0, v1));
                *(__half2*)(SCr + ni * 8) = __floats2half2_rn(v0, v1);
            }
#pragma unroll
            for (int o = 1; o <= 2; o <<= 1)
                rmax = fmaxf(rmax, __shfl_xor_sync(0xFFFFFFFFu, rmax, o));
            if ((lane & 3) == 0)
                atomicMax(&g_tmax[(size_t)(b * T2 + row) * 16 + blockIdx.x], fmono(rmax));
        }
    }
}

// ---------------- K3b: exact candidate rescore (tile-max gated) ----------------
__global__ void k_cand(const float* __restrict__ x) {
    const int b = blockIdx.y;
    const int w = threadIdx.x >> 5;
    const int m = blockIdx.x * 8 + w;
    const int lane = threadIdx.x & 31;
    __shared__ int s_cnt[8];
    __shared__ int s_buf[8][CAND_CAP];
    if (lane == 0) s_cnt[w] = 0;
    __syncwarp();
    const __half* SC = g_SCh + ((size_t)(b * T2) + m) * T2;
    const unsigned* tmx = g_tmax + (size_t)(b * T2 + m) * 16;
    unsigned tm = (lane < 16) ? tmx[lane] : 0u;
    unsigned tall = tm;
#pragma unroll
    for (int o = 16; o; o >>= 1) tall = max(tall, __shfl_xor_sync(0xFFFFFFFFu, tall, o));
    float rmax = imono(tall);
    float thr = rmax - 0.65f;   // 0.5 fp16-quant + 2x GEMM 5-sigma + margin
    unsigned thrm = fmono(thr);
    unsigned qm = __ballot_sync(0xFFFFFFFFu, lane < 16 && tm >= thrm);
    while (qm) {
        int t = __ffs(qm) - 1; qm &= qm - 1;
        const __half2* p = (const __half2*)(SC + t * 128 + lane * 4);
        __half2 h0 = p[0], h1 = p[1];
        float v[4] = {__low2float(h0), __high2float(h0), __low2float(h1), __high2float(h1)};
        float mx = fmaxf(fmaxf(v[0], v[1]), fmaxf(v[2], v[3]));
        if (mx >= thr) {
#pragma unroll
            for (int j = 0; j < 4; j++)
                if (v[j] >= thr) {
                    int idx = atomicAdd(&s_cnt[w], 1);
                    if (idx < CAND_CAP) s_buf[w][idx] = t * 128 + lane * 4 + j;
                }
        }
    }
    __syncwarp();
    int cnt = min(s_cnt[w], CAND_CAP);
    const float* xb = x + (size_t)b * Tn * Dn;
    const float* xs = xb + (size_t)(2 * m + 1) * Dn;
    const float inv_s = g_inv[b * Tn + 2 * m + 1];
    float best = -FLT_MAX; int bcol = 0x7FFFFFFF;
    for (int c = 0; c < cnt; c++) {
        int j = s_buf[w][c];
        const float* xd = xb + (size_t)(2 * j) * Dn;
        float acc = 0.f;
#pragma unroll
        for (int i = 0; i < 4; i++) {
            int k = lane * 4 + i * 128;
            float4 a = *(const float4*)(xs + k);
            float4 d = *(const float4*)(xd + k);
            acc += a.x * d.x + a.y * d.y + a.z * d.z + a.w * d.w;
        }
#pragma unroll
        for (int o = 16; o; o >>= 1) acc += __shfl_xor_sync(0xFFFFFFFFu, acc, o);
        float e = acc * inv_s * g_inv[b * Tn + 2 * j];
        if (e > best || (e == best && j < bcol)) { best = e; bcol = j; }
    }
    if (lane == 0)
        g_key[b * T2 + m] = ((unsigned long long)fmono(best) << 32) | (unsigned)(2047 - bcol);
}

// ---------------- K4: 4-way seeded bisection top-k select + compaction --------------
__global__ __launch_bounds__(1024) void k_select() {
    const int b = blockIdx.x, tid = threadIdx.x;
    const int lane = tid & 31, w = tid >> 5;
    __shared__ int s_cntArr[64];
    __shared__ unsigned s_bitmap[64], s_wpre[64];
    __shared__ int s_warpsum[32];
    __shared__ unsigned s_min, s_max;
    __shared__ int s_ns;

    unsigned long long kv0 = g_key[b * T2 + tid];
    unsigned long long kv1 = g_key[b * T2 + tid + 1024];
    unsigned m0 = (unsigned)(kv0 >> 32), m1 = (unsigned)(kv1 >> 32);
    g_winner_u[b * T2 + tid] = 0ull;
    g_winner_u[b * T2 + tid + 1024] = 0ull;
    ((unsigned*)(g_merged + (size_t)b * Tn))[tid] = 0u;
    if (tid < 64) { s_cntArr[tid] = 0; s_bitmap[tid] = 0u; }
    if (tid == 0) { s_ns = 0; s_min = 0xFFFFFFFFu; s_max = 0u; }
    __syncthreads();

    // seed range with block min/max
    {
        unsigned mn = min(m0, m1), mx = max(m0, m1);
#pragma unroll
        for (int o = 16; o; o >>= 1) {
            mn = min(mn, __shfl_xor_sync(0xFFFFFFFFu, mn, o));
            mx = max(mx, __shfl_xor_sync(0xFFFFFFFFu, mx, o));
        }
        if (lane == 0) { atomicMin(&s_min, mn); atomicMax(&s_max, mx); }
    }
    __syncthreads();

    // 4-way search for vstar = largest v with count(>=v) >= Rn
    unsigned lo = s_min, hi = s_max;
    for (int it = 0; lo < hi; ++it) {
        unsigned d = hi - lo;
        unsigned t1 = lo + (d >> 2) + 1u;
        unsigned t2 = lo + (d >> 1) + 1u;
        unsigned t3 = lo + (d - (d >> 2));
        int c1 = __popc(__ballot_sync(0xFFFFFFFFu, m0 >= t1))
               + __popc(__ballot_sync(0xFFFFFFFFu, m1 >= t1));
        int c2 = __popc(__ballot_sync(0xFFFFFFFFu, m0 >= t2))
               + __popc(__ballot_sync(0xFFFFFFFFu, m1 >= t2));
        int c3 = __popc(__ballot_sync(0xFFFFFFFFu, m0 >= t3))
               + __popc(__ballot_sync(0xFFFFFFFFu, m1 >= t3));
        if (lane == 0) {
            if (c1) atomicAdd(&s_cntArr[it * 3 + 0], c1);
            if (c2) atomicAdd(&s_cntArr[it * 3 + 1], c2);
            if (c3) atomicAdd(&s_cntArr[it * 3 + 2], c3);
        }
        __syncthreads();
        int C1 = s_cntArr[it * 3 + 0], C2 = s_cntArr[it * 3 + 1], C3 = s_cntArr[it * 3 + 2];
        if (C3 >= Rn)      { lo = t3; }
        else if (C2 >= Rn) { lo = t2; hi = t3 - 1u; }
        else if (C1 >= Rn) { lo = t1; hi = t2 - 1u; }
        else               { hi = t1 - 1u; }
    }
    const unsigned vstar = lo;
    {
        int cg = __popc(__ballot_sync(0xFFFFFFFFu, m0 > vstar))
               + __popc(__ballot_sync(0xFFFFFFFFu, m1 > vstar));
        if (lane == 0 && cg) atomicAdd(&s_cntArr[62], cg);
    }
    if (m0 == vstar) atomicOr(&s_bitmap[tid >> 5], 1u << (tid & 31));
    if (m1 == vstar) atomicOr(&s_bitmap[(tid + 1024) >> 5], 1u << (tid & 31));
    __syncthreads();
    const unsigned quota = Rn - (unsigned)s_cntArr[62];
    if (tid == 0) {
        unsigned run = 0;
        for (int w2 = 0; w2 < 64; w2++) { s_wpre[w2] = run; run += __popc(s_bitmap[w2]); }
    }
    __syncthreads();

#pragma unroll
    for (int e = 0; e < 2; e++) {
        int i = tid + e * 1024;
        unsigned mo = e ? m1 : m0;
        unsigned long long kv = e ? kv1 : kv0;
        bool sel = mo > vstar;
        if (!sel && mo == vstar) {
            unsigned r = s_wpre[i >> 5] + __popc(s_bitmap[i >> 5] & ((1u << (i & 31)) - 1u));
            sel = r < quota;
        }
        if (sel) {
            int slot = atomicAdd(&s_ns, 1);
            int stok = 2 * i + 1;
            int dl = 2047 - (int)(kv & 0xFFFFFFFFu);
            g_srctok[b * Rn + slot] = stok;
            g_dsttok[b * Rn + slot] = 2 * dl;
            g_merged[(size_t)b * Tn + stok] = 1;
            unsigned long long wkey = ((unsigned long long)(~mo) << 32) | (unsigned)i;
            atomicMax(&g_winner_u[(size_t)b * T2 + dl], wkey);
        }
    }
    __syncthreads();

    // compaction: warp-shuffle scan
    const int base = tid * 4;
    int loc[4]; int c0 = 0;
#pragma unroll
    for (int i = 0; i < 4; i++) {
        loc[i] = g_merged[(size_t)b * Tn + base + i] ? 0 : 1;
        c0 += loc[i];
    }
    int inc = c0;
#pragma unroll
    for (int o = 1; o < 32; o <<= 1) {
        int v = __shfl_up_sync(0xFFFFFFFFu, inc, o);
        if (lane >= o) inc += v;
    }
    if (lane == 31) s_warpsum[w] = inc;
    __syncthreads();
    if (w == 0) {
        int v = s_warpsum[lane];
        int sc = v;
#pragma unroll
        for (int o = 1; o < 32; o <<= 1) {
            int u = __shfl_up_sync(0xFFFFFFFFu, sc, o);
            if (lane >= o) sc += u;
        }
        s_warpsum[lane] = sc - v;
    }
    __syncthreads();
    int run = s_warpsum[w] + inc - c0;
#pragma unroll
    for (int i = 0; i < 4; i++)
        if (loc[i]) { g_col[b * Cn + run] = base + i; run++; }
}

// ---------------- K6: merged matrix, hi-only fp16 ----------------
__global__ void k_build2(const float* __restrict__ x) {
    const int b = blockIdx.y, c = blockIdx.x;
    const int t = g_col[b * Cn + c];
    const int tid = threadIdx.x; // 128
    const float* xb = x + (size_t)b * Tn * Dn;
    float4 v = *(const float4*)(xb + (size_t)t * Dn + tid * 4);
    if ((t & 1) == 0) {
        unsigned long long w = g_winner_u[(size_t)b * T2 + (t >> 1)];
        if (w) {
            int si = (int)(w & 0xFFFFFFFFu);
            const float4* up = (const float4*)(xb + (size_t)(2 * si + 1) * Dn);
            float4 u = up[tid];
            v.x = (u.x + v.x) * 0.5f; v.y = (u.y + v.y) * 0.5f;
            v.z = (u.z + v.z) * 0.5f; v.w = (u.w + v.w) * 0.5f;
        }
    }
    unsigned short* rp = g_A2 + ((size_t)(b * Cn + c)) * KPA;
    unsigned short hs[4];
    hs[0] = __half_as_ushort(__float2half_rn(v.x));
    hs[1] = __half_as_ushort(__float2half_rn(v.y));
    hs[2] = __half_as_ushort(__float2half_rn(v.z));
    hs[3] = __half_as_ushort(__float2half_rn(v.w));
    *(ushort4*)(rp + tid * 4) = make_ushort4(hs[0], hs[1], hs[2], hs[3]);
}

// ---------------- K7: hidden GEMM (AhWh + AhWm) + scattered epilogue ----------------
__global__ __launch_bounds__(256, 2) void k_hidden_mma(const float* __restrict__ bias,
                                                       float* __restrict__ out) {
    extern __shared__ char smx[];
    const int n0 = blockIdx.x * BN, m0 = blockIdx.y * BM;
    const int b = m0 / Cn, cm0 = m0 % Cn;
    const int tid = threadIdx.x, lane = tid & 31, w = tid >> 5;
    const int wr = w >> 1, wc = w & 1;
    int*   s_tok  = (int*)(smx + 3 * STG_BYTES);
    float* s_bias = (float*)(smx + 3 * STG_BYTES + 512 + 64);
    if (tid < 128) s_tok[tid] = g_col[b * Cn + cm0 + tid];
    if (tid >= 128 && tid < 256) s_bias[tid - 128] = bias[n0 + tid - 128];
    __syncthreads();
    float acc[2][8][4];
    gemm_tile<16, true>(g_A2 + (size_t)m0 * KPA, g_Wt + (size_t)n0 * KPW,
                        KPA, KPW, smem_u32(smx), tid, acc);
#pragma unroll
    for (int mi = 0; mi < 2; mi++) {
#pragma unroll
        for (int hi = 0; hi < 2; hi++) {
            int row = wr * 32 + mi * 16 + (lane >> 2) + hi * 8;
            int tok = s_tok[row];
            float* op = out + (size_t)b * Tn * Dn + (size_t)tok * Dn + n0;
#pragma unroll
            for (int ni = 0; ni < 8; ni++) {
                int col = wc * 64 + ni * 8 + 2 * (lane & 3);
                float2 o;
                o.x = acc[mi][ni][hi * 2 + 0] + s_bias[col + 0];
                o.y = acc[mi][ni][hi * 2 + 1] + s_bias[col + 1];
                *(float2*)(op + col) = o;
            }
        }
    }
}

// ---------------- K8: out[src] = out[dst], 4 pairs per block ----------------
__global__ void k_copy(float* __restrict__ out) {
    const int b = blockIdx.y;
    const int i = blockIdx.x * 4 + (threadIdx.x >> 7);
    const int tid = threadIdx.x & 127;
    const int st = g_srctok[b * Rn + i], dt = g_dsttok[b * Rn + i];
    const float4* src = (const float4*)(out + (size_t)b * Tn * Dn + (size_t)dt * Dn);
    float4* dst = (float4*)(out + (size_t)b * Tn * Dn + (size_t)st * Dn);
    dst[tid] = src[tid];
}

extern "C" void kernel_launch(void* const* d_in, const int* in_sizes, int n_in,
                              void* d_out, int out_size) {
    const float* x    = (const float*)d_in[0];
    const float* W    = (const float*)d_in[1];
    const float* bias = (const float*)d_in[2];
    float* out = (float*)d_out;

    static int cfg = 0;
    if (!cfg) {
        cudaFuncSetAttribute(k_scores_hi, cudaFuncAttributeMaxDynamicSharedMemorySize, SMEM_DYN);
        cudaFuncSetAttribute(k_hidden_mma, cudaFuncAttributeMaxDynamicSharedMemorySize, SMEM_DYN);
        cfg = 1;
    }

    k_prep<<<Bn * Tn / 8, 256>>>(x, W);
    k_scores_hi<<<dim3(T2 / BN, T2 / BM, Bn), 256, SMEM_DYN>>>();
    k_cand<<<dim3(T2 / 8, Bn), 256>>>(x);
    k_select<<<Bn, 1024>>>();
    k_build2<<<dim3(Cn, Bn), 128>>>(x);
    k_hidden_mma<<<dim3(Dn / BN, (Bn * Cn) / BM), 256, SMEM_DYN>>>(bias, out);
    k_copy<<<dim3(Rn / 4, Bn), 512>>>(out);
}